// round 9
// baseline (speedup 1.0000x reference)
#include <cuda_runtime.h>
#include <cstdint>
#include <cstddef>

#define BSZ 32
#define SLEN 4096
#define EMB 256

typedef unsigned long long ull;

// ---------------- device scratch (static, no runtime alloc) ----------------
__device__ float g_wkT[EMB * EMB];          // wk transposed: [i][j]
__device__ float g_eq;                       // tanh(qp)@we_q + be
__device__ float g_energy[BSZ * SLEN];       // per-token energy (mask applied)
__device__ float g_m[BSZ];                   // per-batch max
__device__ float g_d[BSZ];                   // per-batch sum exp
__device__ float g_partial[BSZ * 16 * EMB];  // chunked weighted sums

// ---------------- f32x2 helpers ----------------
__device__ __forceinline__ ull ffma2(ull a, ull b, ull c) {
    ull d;
    asm("fma.rn.f32x2 %0, %1, %2, %3;" : "=l"(d) : "l"(a), "l"(b), "l"(c));
    return d;
}
__device__ __forceinline__ ull dup2(float x) {
    unsigned u = __float_as_uint(x);
    return ((ull)u << 32) | (ull)u;
}
__device__ __forceinline__ float lo2(ull p) { return __uint_as_float((unsigned)p); }
__device__ __forceinline__ float hi2(ull p) { return __uint_as_float((unsigned)(p >> 32)); }

// ---------------- prep: e_q scalar ----------------
__global__ void prep_eq(const float* __restrict__ wquery,
                        const float* __restrict__ wq,
                        const float* __restrict__ bq,
                        const float* __restrict__ we,
                        const float* __restrict__ be) {
    int j = threadIdx.x;  // 256 threads
    float dot = 0.f;
    #pragma unroll 8
    for (int i = 0; i < EMB; i++) dot += wquery[i] * wq[j * EMB + i];
    float qp = fmaxf(dot + bq[j], 0.f);
    float v = tanhf(qp) * we[j];  // we_q = we[0, :256]
    __shared__ float red[256];
    red[j] = v;
    __syncthreads();
    for (int s = 128; s > 0; s >>= 1) {
        if (j < s) red[j] += red[j + s];
        __syncthreads();
    }
    if (j == 0) g_eq = red[0] + be[0];
}

// ---------------- prep: transpose wk ----------------
__global__ void prep_transpose(const float* __restrict__ wk) {
    int i = blockIdx.x, j = threadIdx.x;
    g_wkT[i * EMB + j] = wk[j * EMB + i];
}

// ---------------- main: energy per token ----------------
// Block = 256 threads = 8 warps; 64 tokens per block (8 per warp).
// smem: sWE2 = WE tile duplicated into f32x2 pairs [64 tok][256 i] (128 KB)
//       sWK  = wkT chunk [64 i][256 j] (64 KB)
// Per lane: 8 tokens x 4 j-pairs (j = 2*lane + 64*u, +1) = 32 f32x2 accumulators.
__global__ __launch_bounds__(256, 1)
void energy_kernel(const float* __restrict__ WE,
                   const int* __restrict__ mask,   // bool widened to 4-byte; nonzero = true
                   const float* __restrict__ bk,
                   const float* __restrict__ we) {
    extern __shared__ unsigned char sraw[];
    ull* sWE2 = (ull*)sraw;                        // 64*256 ull = 131072 B
    float* sWK = (float*)(sraw + 64 * 256 * 8);    // 64*256 f32 = 65536 B

    const int tid = threadIdx.x;
    const int w = tid >> 5, l = tid & 31;
    const int tokBase = blockIdx.x * 64;

    // Load WE tile, duplicated to (x,x) pairs. Coalesced reads, conflict-free writes.
    const float4* WEv = (const float4*)WE;
    for (int idx = tid; idx < 4096; idx += 256) {
        int t = idx >> 6, c4 = idx & 63;
        float4 v = WEv[(size_t)(tokBase + t) * 64 + c4];
        ull* dst = &sWE2[t * 256 + c4 * 4];
        dst[0] = dup2(v.x); dst[1] = dup2(v.y);
        dst[2] = dup2(v.z); dst[3] = dup2(v.w);
    }

    ull acc[8][4];
    #pragma unroll
    for (int t = 0; t < 8; t++)
        #pragma unroll
        for (int u = 0; u < 4; u++) acc[t][u] = 0ULL;

    const ull* aBase = &sWE2[w * 8 * 256];

    for (int i0 = 0; i0 < EMB; i0 += 64) {
        __syncthreads();  // previous chunk consumed (also guards sWE2 fill on iter 0)
        const float4* src = (const float4*)(g_wkT + i0 * EMB);
        float4* dstv = (float4*)sWK;
        for (int idx = tid; idx < 4096; idx += 256) dstv[idx] = src[idx];
        __syncthreads();

        #pragma unroll 4
        for (int i = 0; i < 64; i++) {
            ull b[4];
            const ull* brow = (const ull*)&sWK[i * 256];
            #pragma unroll
            for (int u = 0; u < 4; u++) b[u] = brow[l + 32 * u];  // j pair (2l+64u, +1)
            #pragma unroll
            for (int t = 0; t < 8; t++) {
                ull a = aBase[t * 256 + (i0 + i)];  // broadcast LDS.64
                #pragma unroll
                for (int u = 0; u < 4; u++) acc[t][u] = ffma2(a, b[u], acc[t][u]);
            }
        }
    }

    // Epilogue: bias + relu + tanh + dot with we_k, then warp-reduce per token.
    float bk0[4], bk1[4], wk0[4], wk1[4];
    #pragma unroll
    for (int u = 0; u < 4; u++) {
        int j0 = 2 * l + 64 * u;
        float2 bp = *(const float2*)&bk[j0];
        float2 wp = *(const float2*)&we[EMB + j0];  // we_k = we[0, 256:512]
        bk0[u] = bp.x; bk1[u] = bp.y; wk0[u] = wp.x; wk1[u] = wp.y;
    }
    float eq = g_eq;

    float p[8];
    #pragma unroll
    for (int t = 0; t < 8; t++) {
        float s = 0.f;
        #pragma unroll
        for (int u = 0; u < 4; u++) {
            float k0 = fmaxf(lo2(acc[t][u]) + bk0[u], 0.f);
            float k1 = fmaxf(hi2(acc[t][u]) + bk1[u], 0.f);
            s += tanhf(k0) * wk0[u] + tanhf(k1) * wk1[u];
        }
        #pragma unroll
        for (int off = 16; off > 0; off >>= 1)
            s += __shfl_xor_sync(0xffffffffu, s, off);
        p[t] = s;
    }

    if (l < 8) {
        float pv = p[0];
        #pragma unroll
        for (int t = 1; t < 8; t++)
            if (l == t) pv = p[t];
        int tok = tokBase + w * 8 + l;
        // nonzero bit pattern = true (works for int32 0/1 and float32 0.0/1.0)
        bool mv = (mask[tok] != 0);
        // masked positions get literal 1e-45 (≈0, NOT -inf), matching reference
        g_energy[tok] = mv ? (eq + pv) : 1e-45f;
    }
}

// ---------------- per-batch softmax stats ----------------
__global__ void softmax_stats() {
    int b = blockIdx.x;
    int tid = threadIdx.x;
    __shared__ float red[256];

    float m = -1e30f;
    for (int s = tid; s < SLEN; s += 256) m = fmaxf(m, g_energy[b * SLEN + s]);
    red[tid] = m;
    __syncthreads();
    for (int s = 128; s > 0; s >>= 1) {
        if (tid < s) red[tid] = fmaxf(red[tid], red[tid + s]);
        __syncthreads();
    }
    m = red[0];
    __syncthreads();

    float d = 0.f;
    for (int s = tid; s < SLEN; s += 256) d += expf(g_energy[b * SLEN + s] - m);
    red[tid] = d;
    __syncthreads();
    for (int s = 128; s > 0; s >>= 1) {
        if (tid < s) red[tid] += red[tid + s];
        __syncthreads();
    }
    if (tid == 0) { g_m[b] = m; g_d[b] = red[0]; }
}

// ---------------- weighted sum (unnormalized partials) ----------------
__global__ __launch_bounds__(256)
void weighted_partial(const float* __restrict__ WE) {
    int b = blockIdx.x >> 4, c = blockIdx.x & 15;
    int tid = threadIdx.x;
    __shared__ float sw[256];

    int sBase = b * SLEN + c * 256;
    sw[tid] = expf(g_energy[sBase + tid] - g_m[b]);
    __syncthreads();

    const float* base = WE + (size_t)sBase * EMB;
    float acc = 0.f;
    #pragma unroll 8
    for (int s = 0; s < 256; s++)
        acc += sw[s] * base[(size_t)s * EMB + tid];

    g_partial[(b * 16 + c) * EMB + tid] = acc;
}

__global__ void finalize(float* __restrict__ out) {
    int b = blockIdx.x, e = threadIdx.x;
    float s = 0.f;
    #pragma unroll
    for (int c = 0; c < 16; c++) s += g_partial[(b * 16 + c) * EMB + e];
    out[b * EMB + e] = s / g_d[b];
}

// ---------------- launch ----------------
extern "C" void kernel_launch(void* const* d_in, const int* in_sizes, int n_in,
                              void* d_out, int out_size) {
    const float* WE     = (const float*)d_in[0];
    const int*   mask   = (const int*)d_in[1];   // bool widened to 4-byte by harness
    const float* wquery = (const float*)d_in[2];
    const float* wq     = (const float*)d_in[3];
    const float* bq     = (const float*)d_in[4];
    const float* wk     = (const float*)d_in[5];
    const float* bk     = (const float*)d_in[6];
    const float* we     = (const float*)d_in[7];
    const float* be     = (const float*)d_in[8];
    float* out          = (float*)d_out;

    prep_eq<<<1, 256>>>(wquery, wq, bq, we, be);
    prep_transpose<<<256, 256>>>(wk);

    const int smem = 64 * 256 * 8 + 64 * 256 * 4;  // 196608 B
    cudaFuncSetAttribute(energy_kernel,
                         cudaFuncAttributeMaxDynamicSharedMemorySize, smem);
    energy_kernel<<<(BSZ * SLEN) / 64, 256, smem>>>(WE, mask, bk, we);

    softmax_stats<<<BSZ, 256>>>();
    weighted_partial<<<BSZ * 16, 256>>>(WE);
    finalize<<<BSZ, 256>>>(out);
}

// round 13
// speedup vs baseline: 3.0776x; 3.0776x over previous
#include <cuda_runtime.h>
#include <cuda_bf16.h>
#include <cstdint>
#include <cstddef>

#define BSZ 32
#define SLEN 4096
#define EMB 256

// ---------------- device scratch ----------------
// B fragments, fragment-ordered: [nblk(32)][kstep(16)][lane(32)] -> uint2 {b0,b1}
__device__ uint2 g_Bh[32 * 16 * 32];
__device__ uint2 g_Bl[32 * 16 * 32];
__device__ float g_eq;
__device__ float g_energy[BSZ * SLEN];
__device__ float g_m[BSZ];
__device__ float g_d[BSZ];
__device__ float g_partial[BSZ * 16 * EMB];

// ---------------- helpers ----------------
__device__ __forceinline__ uint32_t pack_bf16(float lo_elem, float hi_elem) {
    // returns b32 with lo_elem in bits[0:16), hi_elem in bits[16:32)
    __nv_bfloat16 a = __float2bfloat16_rn(lo_elem);
    __nv_bfloat16 b = __float2bfloat16_rn(hi_elem);
    return (uint32_t)__bfloat16_as_ushort(a) | ((uint32_t)__bfloat16_as_ushort(b) << 16);
}

__device__ __forceinline__ void mma16816(float c[4], const uint32_t* a,
                                         uint32_t b0, uint32_t b1) {
    asm volatile(
        "mma.sync.aligned.m16n8k16.row.col.f32.bf16.bf16.f32 "
        "{%0,%1,%2,%3}, {%4,%5,%6,%7}, {%8,%9}, {%0,%1,%2,%3};"
        : "+f"(c[0]), "+f"(c[1]), "+f"(c[2]), "+f"(c[3])
        : "r"(a[0]), "r"(a[1]), "r"(a[2]), "r"(a[3]), "r"(b0), "r"(b1));
}

// fast tanh for x >= 0 (post-relu): 1 - 2/(e^{2x}+1); exact at 0, ->1 for large x
__device__ __forceinline__ float ftanh_nn(float x) {
    float e = __expf(2.0f * x);
    return 1.0f - __fdividef(2.0f, e + 1.0f);
}

// ---------------- prep: e_q scalar ----------------
__global__ void prep_eq(const float* __restrict__ wquery, const float* __restrict__ wq,
                        const float* __restrict__ bq, const float* __restrict__ we,
                        const float* __restrict__ be) {
    int j = threadIdx.x;
    float dot = 0.f;
    #pragma unroll 8
    for (int i = 0; i < EMB; i++) dot += wquery[i] * wq[j * EMB + i];
    float qp = fmaxf(dot + bq[j], 0.f);
    float v = tanhf(qp) * we[j];
    __shared__ float red[256];
    red[j] = v;
    __syncthreads();
    for (int s = 128; s > 0; s >>= 1) {
        if (j < s) red[j] += red[j + s];
        __syncthreads();
    }
    if (j == 0) g_eq = red[0] + be[0];
}

// ---------------- prep: wk -> bf16 hi/lo B fragments ----------------
// B operand (col) for m16n8k16: lane(g= l>>2, t= l&3) holds
//   b0 = {B[k=t*2][n=g], B[t*2+1][g]},  b1 = {B[t*2+8][g], B[t*2+9][g]}
// with B[k][n] = wk[n][k].
__global__ void prep_wkB(const float* __restrict__ wk) {
    int idx = blockIdx.x * 256 + threadIdx.x;   // 0..16383
    int lane = idx & 31;
    int ks = (idx >> 5) & 15;
    int nblk = idx >> 9;
    int g = lane >> 2, t = lane & 3;
    int n = nblk * 8 + g;
    int k = ks * 16 + t * 2;
    const float* row = wk + n * EMB;
    float x0 = row[k], x1 = row[k + 1], x2 = row[k + 8], x3 = row[k + 9];

    __nv_bfloat16 h0 = __float2bfloat16_rn(x0), h1 = __float2bfloat16_rn(x1);
    __nv_bfloat16 h2 = __float2bfloat16_rn(x2), h3 = __float2bfloat16_rn(x3);
    float l0 = x0 - __bfloat162float(h0), l1 = x1 - __bfloat162float(h1);
    float l2 = x2 - __bfloat162float(h2), l3 = x3 - __bfloat162float(h3);

    uint2 bh, bl;
    bh.x = (uint32_t)__bfloat16_as_ushort(h0) | ((uint32_t)__bfloat16_as_ushort(h1) << 16);
    bh.y = (uint32_t)__bfloat16_as_ushort(h2) | ((uint32_t)__bfloat16_as_ushort(h3) << 16);
    bl.x = pack_bf16(l0, l1);
    bl.y = pack_bf16(l2, l3);
    g_Bh[idx] = bh;
    g_Bl[idx] = bl;
}

// ---------------- main: energy via mma.sync (HMMA) ----------------
// Block: 256 thr (8 warps), M=64 tokens, N=256 (warp nw covers n in [nw*32, nw*32+32)).
// A tile converted once to smem in fragment order:
//   sA[mf(4)][ks(16)][lane(32)][reg(4)] (uint, bf16x2), hi and lo planes.
#define SM_AH 0
#define SM_AL 32768
#define SM_BK 65536
#define SM_WE 66560
#define SM_SE 67584
#define SMEM_TOTAL (67584 + 64 * 8 * 4)   // 69632

__global__ __launch_bounds__(256, 2)
void energy_kernel(const float* __restrict__ WE,
                   const int* __restrict__ mask,
                   const float* __restrict__ bk,
                   const float* __restrict__ we) {
    extern __shared__ unsigned char sm[];
    uint32_t* sAhi = (uint32_t*)(sm + SM_AH);
    uint32_t* sAlo = (uint32_t*)(sm + SM_AL);
    float* sBk = (float*)(sm + SM_BK);
    float* sWe = (float*)(sm + SM_WE);
    float* sE  = (float*)(sm + SM_SE);    // [64][8]

    const int tid = threadIdx.x;
    const int nw = tid >> 5;              // warp id = n-slice 0..7
    const int lane = tid & 31;
    const int g = lane >> 2, t = lane & 3;
    const int tokBase = blockIdx.x * 64;

    sBk[tid] = bk[tid];
    sWe[tid] = we[EMB + tid];

    // ---- convert A tile (64 x 256 fp32) -> bf16 hi/lo fragments in smem ----
    for (int idx = tid; idx < 8192; idx += 256) {
        int r = idx >> 7, kp = idx & 127;
        float2 f = *(const float2*)(WE + (size_t)(tokBase + r) * EMB + kp * 2);
        __nv_bfloat16 h0 = __float2bfloat16_rn(f.x);
        __nv_bfloat16 h1 = __float2bfloat16_rn(f.y);
        float l0 = f.x - __bfloat162float(h0);
        float l1 = f.y - __bfloat162float(h1);
        uint32_t hp = (uint32_t)__bfloat16_as_ushort(h0) |
                      ((uint32_t)__bfloat16_as_ushort(h1) << 16);
        uint32_t lp = pack_bf16(l0, l1);
        // fragment coords: row r -> mf=r>>4, g8=r&7, ahalf=(r>>3)&1
        //                  k = 2*kp -> ks=kp>>3, t=kp&3, khigh=(kp>>2)&1
        int mf = r >> 4, g8 = r & 7, ah = (r >> 3) & 1;
        int ks = kp >> 3, tt = kp & 3, kh = (kp >> 2) & 1;
        int off = (((mf * 16 + ks) * 32) + (g8 * 4 + tt)) * 4 + (ah + kh * 2);
        sAhi[off] = hp;
        sAlo[off] = lp;
    }
    __syncthreads();

    // ---- mainloop: D = Ah*Bh + Ah*Bl + Al*Bh ----
    float c[4][4][4];
    #pragma unroll
    for (int mf = 0; mf < 4; mf++)
        #pragma unroll
        for (int nb = 0; nb < 4; nb++)
            #pragma unroll
            for (int r = 0; r < 4; r++) c[mf][nb][r] = 0.f;

    #pragma unroll 1
    for (int ks = 0; ks < 16; ks++) {
        uint4 ahv[4], alv[4];
        #pragma unroll
        for (int mf = 0; mf < 4; mf++) {
            int fo = ((mf * 16 + ks) * 32 + lane) * 4;
            ahv[mf] = *(const uint4*)(sAhi + fo);
            alv[mf] = *(const uint4*)(sAlo + fo);
        }
        #pragma unroll
        for (int nb = 0; nb < 4; nb++) {
            int fidx = ((nw * 4 + nb) * 16 + ks) * 32 + lane;
            uint2 bh = g_Bh[fidx];
            uint2 bl = g_Bl[fidx];
            #pragma unroll
            for (int mf = 0; mf < 4; mf++) {
                mma16816(c[mf][nb], (const uint32_t*)&ahv[mf], bh.x, bh.y);
                mma16816(c[mf][nb], (const uint32_t*)&ahv[mf], bl.x, bl.y);
                mma16816(c[mf][nb], (const uint32_t*)&alv[mf], bh.x, bh.y);
            }
        }
    }

    // ---- epilogue: bias + relu + tanh + dot(we_k) ----
    // lane's elements: rows mf*16+g (c0,c1) and mf*16+g+8 (c2,c3);
    // cols j = nw*32 + nb*8 + t*2 + {0,1}
    float rs[4][2];
    #pragma unroll
    for (int mf = 0; mf < 4; mf++) { rs[mf][0] = 0.f; rs[mf][1] = 0.f; }

    #pragma unroll
    for (int nb = 0; nb < 4; nb++) {
        int j0 = nw * 32 + nb * 8 + t * 2;
        float b0 = sBk[j0], b1 = sBk[j0 + 1];
        float w0 = sWe[j0], w1 = sWe[j0 + 1];
        #pragma unroll
        for (int mf = 0; mf < 4; mf++) {
            rs[mf][0] += ftanh_nn(fmaxf(c[mf][nb][0] + b0, 0.f)) * w0
                       + ftanh_nn(fmaxf(c[mf][nb][1] + b1, 0.f)) * w1;
            rs[mf][1] += ftanh_nn(fmaxf(c[mf][nb][2] + b0, 0.f)) * w0
                       + ftanh_nn(fmaxf(c[mf][nb][3] + b1, 0.f)) * w1;
        }
    }

    #pragma unroll
    for (int mf = 0; mf < 4; mf++) {
        #pragma unroll
        for (int h = 0; h < 2; h++) {
            float v = rs[mf][h];
            v += __shfl_xor_sync(0xffffffffu, v, 1);
            v += __shfl_xor_sync(0xffffffffu, v, 2);
            if (t == 0) sE[(mf * 16 + h * 8 + g) * 8 + nw] = v;
        }
    }
    __syncthreads();

    if (tid < 64) {
        float e = 0.f;
        #pragma unroll
        for (int q = 0; q < 8; q++) e += sE[tid * 8 + q];
        int token = tokBase + tid;
        bool mv = (mask[token] != 0);
        g_energy[token] = mv ? (g_eq + e) : 1e-45f;
    }
}

// ---------------- per-batch softmax stats ----------------
__global__ void softmax_stats() {
    int b = blockIdx.x;
    int tid = threadIdx.x;
    __shared__ float red[256];

    float m = -1e30f;
    for (int s = tid; s < SLEN; s += 256) m = fmaxf(m, g_energy[b * SLEN + s]);
    red[tid] = m;
    __syncthreads();
    for (int s = 128; s > 0; s >>= 1) {
        if (tid < s) red[tid] = fmaxf(red[tid], red[tid + s]);
        __syncthreads();
    }
    m = red[0];
    __syncthreads();

    float d = 0.f;
    for (int s = tid; s < SLEN; s += 256) d += expf(g_energy[b * SLEN + s] - m);
    red[tid] = d;
    __syncthreads();
    for (int s = 128; s > 0; s >>= 1) {
        if (tid < s) red[tid] += red[tid + s];
        __syncthreads();
    }
    if (tid == 0) { g_m[b] = m; g_d[b] = red[0]; }
}

// ---------------- weighted sum (unnormalized partials) ----------------
__global__ __launch_bounds__(256)
void weighted_partial(const float* __restrict__ WE) {
    int b = blockIdx.x >> 4, c = blockIdx.x & 15;
    int tid = threadIdx.x;
    __shared__ float sw[256];

    int sBase = b * SLEN + c * 256;
    sw[tid] = expf(g_energy[sBase + tid] - g_m[b]);
    __syncthreads();

    const float* base = WE + (size_t)sBase * EMB;
    float acc = 0.f;
    #pragma unroll 8
    for (int s = 0; s < 256; s++)
        acc += sw[s] * base[(size_t)s * EMB + tid];

    g_partial[(b * 16 + c) * EMB + tid] = acc;
}

__global__ void finalize(float* __restrict__ out) {
    int b = blockIdx.x, e = threadIdx.x;
    float s = 0.f;
    #pragma unroll
    for (int c = 0; c < 16; c++) s += g_partial[(b * 16 + c) * EMB + e];
    out[b * EMB + e] = s / g_d[b];
}

// ---------------- launch ----------------
extern "C" void kernel_launch(void* const* d_in, const int* in_sizes, int n_in,
                              void* d_out, int out_size) {
    const float* WE     = (const float*)d_in[0];
    const int*   mask   = (const int*)d_in[1];
    const float* wquery = (const float*)d_in[2];
    const float* wq     = (const float*)d_in[3];
    const float* bq     = (const float*)d_in[4];
    const float* wk     = (const float*)d_in[5];
    const float* bk     = (const float*)d_in[6];
    const float* we     = (const float*)d_in[7];
    const float* be     = (const float*)d_in[8];
    float* out          = (float*)d_out;

    prep_eq<<<1, 256>>>(wquery, wq, bq, we, be);
    prep_wkB<<<64, 256>>>(wk);

    cudaFuncSetAttribute(energy_kernel,
                         cudaFuncAttributeMaxDynamicSharedMemorySize, SMEM_TOTAL);
    energy_kernel<<<(BSZ * SLEN) / 64, 256, SMEM_TOTAL>>>(WE, mask, bk, we);

    softmax_stats<<<BSZ, 256>>>();
    weighted_partial<<<BSZ * 16, 256>>>(WE);
    finalize<<<BSZ, 256>>>(out);
}

// round 14
// speedup vs baseline: 3.0919x; 1.0047x over previous
#include <cuda_runtime.h>
#include <cuda_bf16.h>
#include <cstdint>
#include <cstddef>

#define BSZ 32
#define SLEN 4096
#define EMB 256

// ---------------- device scratch ----------------
// B fragments, fragment-ordered: [nblk(32)][kstep(16)][lane(32)] -> uint2 {b0,b1}
__device__ uint2 g_Bh[32 * 16 * 32];
__device__ uint2 g_Bl[32 * 16 * 32];
__device__ float g_eq;
__device__ float g_energy[BSZ * SLEN];
__device__ float g_m[BSZ];
__device__ float g_d[BSZ];
__device__ float g_partial[BSZ * 16 * EMB];

// ---------------- helpers ----------------
__device__ __forceinline__ uint32_t pack_bf16(float lo_elem, float hi_elem) {
    // returns b32 with lo_elem in bits[0:16), hi_elem in bits[16:32)
    __nv_bfloat16 a = __float2bfloat16_rn(lo_elem);
    __nv_bfloat16 b = __float2bfloat16_rn(hi_elem);
    return (uint32_t)__bfloat16_as_ushort(a) | ((uint32_t)__bfloat16_as_ushort(b) << 16);
}

__device__ __forceinline__ void mma16816(float c[4], const uint32_t* a,
                                         uint32_t b0, uint32_t b1) {
    asm volatile(
        "mma.sync.aligned.m16n8k16.row.col.f32.bf16.bf16.f32 "
        "{%0,%1,%2,%3}, {%4,%5,%6,%7}, {%8,%9}, {%0,%1,%2,%3};"
        : "+f"(c[0]), "+f"(c[1]), "+f"(c[2]), "+f"(c[3])
        : "r"(a[0]), "r"(a[1]), "r"(a[2]), "r"(a[3]), "r"(b0), "r"(b1));
}

// fast tanh for x >= 0 (post-relu): 1 - 2/(e^{2x}+1); exact at 0, ->1 for large x
__device__ __forceinline__ float ftanh_nn(float x) {
    float e = __expf(2.0f * x);
    return 1.0f - __fdividef(2.0f, e + 1.0f);
}

// ---------------- prep: e_q scalar ----------------
__global__ void prep_eq(const float* __restrict__ wquery, const float* __restrict__ wq,
                        const float* __restrict__ bq, const float* __restrict__ we,
                        const float* __restrict__ be) {
    int j = threadIdx.x;
    float dot = 0.f;
    #pragma unroll 8
    for (int i = 0; i < EMB; i++) dot += wquery[i] * wq[j * EMB + i];
    float qp = fmaxf(dot + bq[j], 0.f);
    float v = tanhf(qp) * we[j];
    __shared__ float red[256];
    red[j] = v;
    __syncthreads();
    for (int s = 128; s > 0; s >>= 1) {
        if (j < s) red[j] += red[j + s];
        __syncthreads();
    }
    if (j == 0) g_eq = red[0] + be[0];
}

// ---------------- prep: wk -> bf16 hi/lo B fragments ----------------
// B operand (col) for m16n8k16: lane(g= l>>2, t= l&3) holds
//   b0 = {B[k=t*2][n=g], B[t*2+1][g]},  b1 = {B[t*2+8][g], B[t*2+9][g]}
// with B[k][n] = wk[n][k].
__global__ void prep_wkB(const float* __restrict__ wk) {
    int idx = blockIdx.x * 256 + threadIdx.x;   // 0..16383
    int lane = idx & 31;
    int ks = (idx >> 5) & 15;
    int nblk = idx >> 9;
    int g = lane >> 2, t = lane & 3;
    int n = nblk * 8 + g;
    int k = ks * 16 + t * 2;
    const float* row = wk + n * EMB;
    float x0 = row[k], x1 = row[k + 1], x2 = row[k + 8], x3 = row[k + 9];

    __nv_bfloat16 h0 = __float2bfloat16_rn(x0), h1 = __float2bfloat16_rn(x1);
    __nv_bfloat16 h2 = __float2bfloat16_rn(x2), h3 = __float2bfloat16_rn(x3);
    float l0 = x0 - __bfloat162float(h0), l1 = x1 - __bfloat162float(h1);
    float l2 = x2 - __bfloat162float(h2), l3 = x3 - __bfloat162float(h3);

    uint2 bh, bl;
    bh.x = (uint32_t)__bfloat16_as_ushort(h0) | ((uint32_t)__bfloat16_as_ushort(h1) << 16);
    bh.y = (uint32_t)__bfloat16_as_ushort(h2) | ((uint32_t)__bfloat16_as_ushort(h3) << 16);
    bl.x = pack_bf16(l0, l1);
    bl.y = pack_bf16(l2, l3);
    g_Bh[idx] = bh;
    g_Bl[idx] = bl;
}

// ---------------- main: energy via mma.sync (HMMA) ----------------
// Block: 256 thr (8 warps), M=64 tokens, N=256 (warp nw covers n in [nw*32, nw*32+32)).
// A tile converted once to smem in fragment order:
//   sA[mf(4)][ks(16)][lane(32)][reg(4)] (uint, bf16x2), hi and lo planes.
#define SM_AH 0
#define SM_AL 32768
#define SM_BK 65536
#define SM_WE 66560
#define SM_SE 67584
#define SMEM_TOTAL (67584 + 64 * 8 * 4)   // 69632

__global__ __launch_bounds__(256, 2)
void energy_kernel(const float* __restrict__ WE,
                   const int* __restrict__ mask,
                   const float* __restrict__ bk,
                   const float* __restrict__ we) {
    extern __shared__ unsigned char sm[];
    uint32_t* sAhi = (uint32_t*)(sm + SM_AH);
    uint32_t* sAlo = (uint32_t*)(sm + SM_AL);
    float* sBk = (float*)(sm + SM_BK);
    float* sWe = (float*)(sm + SM_WE);
    float* sE  = (float*)(sm + SM_SE);    // [64][8]

    const int tid = threadIdx.x;
    const int nw = tid >> 5;              // warp id = n-slice 0..7
    const int lane = tid & 31;
    const int g = lane >> 2, t = lane & 3;
    const int tokBase = blockIdx.x * 64;

    sBk[tid] = bk[tid];
    sWe[tid] = we[EMB + tid];

    // ---- convert A tile (64 x 256 fp32) -> bf16 hi/lo fragments in smem ----
    for (int idx = tid; idx < 8192; idx += 256) {
        int r = idx >> 7, kp = idx & 127;
        float2 f = *(const float2*)(WE + (size_t)(tokBase + r) * EMB + kp * 2);
        __nv_bfloat16 h0 = __float2bfloat16_rn(f.x);
        __nv_bfloat16 h1 = __float2bfloat16_rn(f.y);
        float l0 = f.x - __bfloat162float(h0);
        float l1 = f.y - __bfloat162float(h1);
        uint32_t hp = (uint32_t)__bfloat16_as_ushort(h0) |
                      ((uint32_t)__bfloat16_as_ushort(h1) << 16);
        uint32_t lp = pack_bf16(l0, l1);
        // fragment coords: row r -> mf=r>>4, g8=r&7, ahalf=(r>>3)&1
        //                  k = 2*kp -> ks=kp>>3, t=kp&3, khigh=(kp>>2)&1
        int mf = r >> 4, g8 = r & 7, ah = (r >> 3) & 1;
        int ks = kp >> 3, tt = kp & 3, kh = (kp >> 2) & 1;
        int off = (((mf * 16 + ks) * 32) + (g8 * 4 + tt)) * 4 + (ah + kh * 2);
        sAhi[off] = hp;
        sAlo[off] = lp;
    }
    __syncthreads();

    // ---- mainloop: D = Ah*Bh + Ah*Bl + Al*Bh ----
    float c[4][4][4];
    #pragma unroll
    for (int mf = 0; mf < 4; mf++)
        #pragma unroll
        for (int nb = 0; nb < 4; nb++)
            #pragma unroll
            for (int r = 0; r < 4; r++) c[mf][nb][r] = 0.f;

    #pragma unroll 1
    for (int ks = 0; ks < 16; ks++) {
        uint4 ahv[4], alv[4];
        #pragma unroll
        for (int mf = 0; mf < 4; mf++) {
            int fo = ((mf * 16 + ks) * 32 + lane) * 4;
            ahv[mf] = *(const uint4*)(sAhi + fo);
            alv[mf] = *(const uint4*)(sAlo + fo);
        }
        #pragma unroll
        for (int nb = 0; nb < 4; nb++) {
            int fidx = ((nw * 4 + nb) * 16 + ks) * 32 + lane;
            uint2 bh = g_Bh[fidx];
            uint2 bl = g_Bl[fidx];
            #pragma unroll
            for (int mf = 0; mf < 4; mf++) {
                mma16816(c[mf][nb], (const uint32_t*)&ahv[mf], bh.x, bh.y);
                mma16816(c[mf][nb], (const uint32_t*)&ahv[mf], bl.x, bl.y);
                mma16816(c[mf][nb], (const uint32_t*)&alv[mf], bh.x, bh.y);
            }
        }
    }

    // ---- epilogue: bias + relu + tanh + dot(we_k) ----
    // lane's elements: rows mf*16+g (c0,c1) and mf*16+g+8 (c2,c3);
    // cols j = nw*32 + nb*8 + t*2 + {0,1}
    float rs[4][2];
    #pragma unroll
    for (int mf = 0; mf < 4; mf++) { rs[mf][0] = 0.f; rs[mf][1] = 0.f; }

    #pragma unroll
    for (int nb = 0; nb < 4; nb++) {
        int j0 = nw * 32 + nb * 8 + t * 2;
        float b0 = sBk[j0], b1 = sBk[j0 + 1];
        float w0 = sWe[j0], w1 = sWe[j0 + 1];
        #pragma unroll
        for (int mf = 0; mf < 4; mf++) {
            rs[mf][0] += ftanh_nn(fmaxf(c[mf][nb][0] + b0, 0.f)) * w0
                       + ftanh_nn(fmaxf(c[mf][nb][1] + b1, 0.f)) * w1;
            rs[mf][1] += ftanh_nn(fmaxf(c[mf][nb][2] + b0, 0.f)) * w0
                       + ftanh_nn(fmaxf(c[mf][nb][3] + b1, 0.f)) * w1;
        }
    }

    #pragma unroll
    for (int mf = 0; mf < 4; mf++) {
        #pragma unroll
        for (int h = 0; h < 2; h++) {
            float v = rs[mf][h];
            v += __shfl_xor_sync(0xffffffffu, v, 1);
            v += __shfl_xor_sync(0xffffffffu, v, 2);
            if (t == 0) sE[(mf * 16 + h * 8 + g) * 8 + nw] = v;
        }
    }
    __syncthreads();

    if (tid < 64) {
        float e = 0.f;
        #pragma unroll
        for (int q = 0; q < 8; q++) e += sE[tid * 8 + q];
        int token = tokBase + tid;
        bool mv = (mask[token] != 0);
        g_energy[token] = mv ? (g_eq + e) : 1e-45f;
    }
}

// ---------------- per-batch softmax stats ----------------
__global__ void softmax_stats() {
    int b = blockIdx.x;
    int tid = threadIdx.x;
    __shared__ float red[256];

    float m = -1e30f;
    for (int s = tid; s < SLEN; s += 256) m = fmaxf(m, g_energy[b * SLEN + s]);
    red[tid] = m;
    __syncthreads();
    for (int s = 128; s > 0; s >>= 1) {
        if (tid < s) red[tid] = fmaxf(red[tid], red[tid + s]);
        __syncthreads();
    }
    m = red[0];
    __syncthreads();

    float d = 0.f;
    for (int s = tid; s < SLEN; s += 256) d += expf(g_energy[b * SLEN + s] - m);
    red[tid] = d;
    __syncthreads();
    for (int s = 128; s > 0; s >>= 1) {
        if (tid < s) red[tid] += red[tid + s];
        __syncthreads();
    }
    if (tid == 0) { g_m[b] = m; g_d[b] = red[0]; }
}

// ---------------- weighted sum (unnormalized partials) ----------------
__global__ __launch_bounds__(256)
void weighted_partial(const float* __restrict__ WE) {
    int b = blockIdx.x >> 4, c = blockIdx.x & 15;
    int tid = threadIdx.x;
    __shared__ float sw[256];

    int sBase = b * SLEN + c * 256;
    sw[tid] = expf(g_energy[sBase + tid] - g_m[b]);
    __syncthreads();

    const float* base = WE + (size_t)sBase * EMB;
    float acc = 0.f;
    #pragma unroll 8
    for (int s = 0; s < 256; s++)
        acc += sw[s] * base[(size_t)s * EMB + tid];

    g_partial[(b * 16 + c) * EMB + tid] = acc;
}

__global__ void finalize(float* __restrict__ out) {
    int b = blockIdx.x, e = threadIdx.x;
    float s = 0.f;
    #pragma unroll
    for (int c = 0; c < 16; c++) s += g_partial[(b * 16 + c) * EMB + e];
    out[b * EMB + e] = s / g_d[b];
}

// ---------------- launch ----------------
extern "C" void kernel_launch(void* const* d_in, const int* in_sizes, int n_in,
                              void* d_out, int out_size) {
    const float* WE     = (const float*)d_in[0];
    const int*   mask   = (const int*)d_in[1];
    const float* wquery = (const float*)d_in[2];
    const float* wq     = (const float*)d_in[3];
    const float* bq     = (const float*)d_in[4];
    const float* wk     = (const float*)d_in[5];
    const float* bk     = (const float*)d_in[6];
    const float* we     = (const float*)d_in[7];
    const float* be     = (const float*)d_in[8];
    float* out          = (float*)d_out;

    prep_eq<<<1, 256>>>(wquery, wq, bq, we, be);
    prep_wkB<<<64, 256>>>(wk);

    cudaFuncSetAttribute(energy_kernel,
                         cudaFuncAttributeMaxDynamicSharedMemorySize, SMEM_TOTAL);
    energy_kernel<<<(BSZ * SLEN) / 64, 256, SMEM_TOTAL>>>(WE, mask, bk, we);

    softmax_stats<<<BSZ, 256>>>();
    weighted_partial<<<BSZ * 16, 256>>>(WE);
    finalize<<<BSZ, 256>>>(out);
}

// round 15
// speedup vs baseline: 3.4478x; 1.1151x over previous
#include <cuda_runtime.h>
#include <cuda_bf16.h>
#include <cstdint>
#include <cstddef>

#define BSZ 32
#define SLEN 4096
#define EMB 256

// ---------------- device scratch ----------------
// B fragments, fragment-ordered: [nblk(32)][kstep(16)][lane(32)] -> uint2 {b0,b1}
__device__ uint2 g_Bh[32 * 16 * 32];
__device__ uint2 g_Bl[32 * 16 * 32];
__device__ float g_eq;
__device__ float g_d[BSZ];                      // softmax denominators (atomic)
__device__ float g_partial[2048 * EMB];         // per-block weighted partials

// ---------------- helpers ----------------
__device__ __forceinline__ uint32_t pack_bf16(float lo_elem, float hi_elem) {
    __nv_bfloat16 a = __float2bfloat16_rn(lo_elem);
    __nv_bfloat16 b = __float2bfloat16_rn(hi_elem);
    return (uint32_t)__bfloat16_as_ushort(a) | ((uint32_t)__bfloat16_as_ushort(b) << 16);
}
__device__ __forceinline__ float2 unpack_bf16x2(uint32_t v) {
    __nv_bfloat162 b = *(__nv_bfloat162*)&v;
    return __bfloat1622float2(b);
}

__device__ __forceinline__ void mma16816(float c[4], const uint32_t* a,
                                         uint32_t b0, uint32_t b1) {
    asm volatile(
        "mma.sync.aligned.m16n8k16.row.col.f32.bf16.bf16.f32 "
        "{%0,%1,%2,%3}, {%4,%5,%6,%7}, {%8,%9}, {%0,%1,%2,%3};"
        : "+f"(c[0]), "+f"(c[1]), "+f"(c[2]), "+f"(c[3])
        : "r"(a[0]), "r"(a[1]), "r"(a[2]), "r"(a[3]), "r"(b0), "r"(b1));
}

// fast tanh for x >= 0 (post-relu): 1 - 2/(e^{2x}+1)
__device__ __forceinline__ float ftanh_nn(float x) {
    float e = __expf(2.0f * x);
    return 1.0f - __fdividef(2.0f, e + 1.0f);
}

// ---------------- prep: e_q scalar (coalesced) + zero denominators ----------------
__global__ void prep_eq(const float* __restrict__ wquery, const float* __restrict__ wq,
                        const float* __restrict__ bq, const float* __restrict__ we,
                        const float* __restrict__ be) {
    int tid = threadIdx.x;
    int w = tid >> 5, lane = tid & 31;

    if (tid < BSZ) g_d[tid] = 0.f;   // zero denominators for this run

    float4 q0 = ((const float4*)wquery)[lane * 2];
    float4 q1 = ((const float4*)wquery)[lane * 2 + 1];

    float acc = 0.f;
    for (int r = w; r < EMB; r += 8) {
        const float4* row = (const float4*)(wq + (size_t)r * EMB);
        float4 a0 = row[lane * 2], a1 = row[lane * 2 + 1];
        float d = a0.x * q0.x + a0.y * q0.y + a0.z * q0.z + a0.w * q0.w
                + a1.x * q1.x + a1.y * q1.y + a1.z * q1.z + a1.w * q1.w;
        #pragma unroll
        for (int off = 16; off > 0; off >>= 1) d += __shfl_xor_sync(0xffffffffu, d, off);
        if (lane == 0) acc += tanhf(fmaxf(d + bq[r], 0.f)) * we[r];
    }
    __shared__ float red[8];
    if (lane == 0) red[w] = acc;
    __syncthreads();
    if (tid == 0) {
        float s = 0.f;
        #pragma unroll
        for (int q = 0; q < 8; q++) s += red[q];
        g_eq = s + be[0];
    }
}

// ---------------- prep: wk -> bf16 hi/lo B fragments ----------------
__global__ void prep_wkB(const float* __restrict__ wk) {
    int idx = blockIdx.x * 256 + threadIdx.x;   // 0..16383
    int lane = idx & 31;
    int ks = (idx >> 5) & 15;
    int nblk = idx >> 9;
    int g = lane >> 2, t = lane & 3;
    int n = nblk * 8 + g;
    int k = ks * 16 + t * 2;
    const float* row = wk + n * EMB;
    float x0 = row[k], x1 = row[k + 1], x2 = row[k + 8], x3 = row[k + 9];

    __nv_bfloat16 h0 = __float2bfloat16_rn(x0), h1 = __float2bfloat16_rn(x1);
    __nv_bfloat16 h2 = __float2bfloat16_rn(x2), h3 = __float2bfloat16_rn(x3);
    float l0 = x0 - __bfloat162float(h0), l1 = x1 - __bfloat162float(h1);
    float l2 = x2 - __bfloat162float(h2), l3 = x3 - __bfloat162float(h3);

    uint2 bh, bl;
    bh.x = (uint32_t)__bfloat16_as_ushort(h0) | ((uint32_t)__bfloat16_as_ushort(h1) << 16);
    bh.y = (uint32_t)__bfloat16_as_ushort(h2) | ((uint32_t)__bfloat16_as_ushort(h3) << 16);
    bl.x = pack_bf16(l0, l1);
    bl.y = pack_bf16(l2, l3);
    g_Bh[idx] = bh;
    g_Bl[idx] = bl;
}

// ---------------- main: fused energy + exp + denom + weighted partial ----------------
// Block: 256 thr (8 warps), M=64 tokens, N=256 (warp nw covers n slice of 32).
// A tile converted once to bf16 hi/lo fragments in smem (also reused for the
// weighted-sum epilogue: hi+lo reconstructs fp32 to ~2^-18).
#define SM_AH 0
#define SM_AL 32768
#define SM_BK 65536
#define SM_WE 66560
#define SM_SE 67584                      // [64][8] energy partials; reused as sP
#define SM_W  69632                      // [64] exp weights
#define SMEM_TOTAL (69632 + 256)

__global__ __launch_bounds__(256, 2)
void energy_kernel(const float* __restrict__ WE,
                   const int* __restrict__ mask,
                   const float* __restrict__ bk,
                   const float* __restrict__ we) {
    extern __shared__ unsigned char sm[];
    uint32_t* sAhi = (uint32_t*)(sm + SM_AH);
    uint32_t* sAlo = (uint32_t*)(sm + SM_AL);
    float* sBk = (float*)(sm + SM_BK);
    float* sWe = (float*)(sm + SM_WE);
    float* sE  = (float*)(sm + SM_SE);    // [64][8]
    float* sP  = (float*)(sm + SM_SE);    // reused after energies read
    float* sW  = (float*)(sm + SM_W);     // [64] exp weights

    const int tid = threadIdx.x;
    const int nw = tid >> 5;
    const int lane = tid & 31;
    const int g = lane >> 2, t = lane & 3;
    const int tokBase = blockIdx.x * 64;

    sBk[tid] = bk[tid];
    sWe[tid] = we[EMB + tid];

    // ---- convert A tile (64 x 256 fp32) -> bf16 hi/lo fragments in smem ----
    for (int idx = tid; idx < 8192; idx += 256) {
        int r = idx >> 7, kp = idx & 127;
        float2 f = *(const float2*)(WE + (size_t)(tokBase + r) * EMB + kp * 2);
        __nv_bfloat16 h0 = __float2bfloat16_rn(f.x);
        __nv_bfloat16 h1 = __float2bfloat16_rn(f.y);
        float l0 = f.x - __bfloat162float(h0);
        float l1 = f.y - __bfloat162float(h1);
        uint32_t hp = (uint32_t)__bfloat16_as_ushort(h0) |
                      ((uint32_t)__bfloat16_as_ushort(h1) << 16);
        uint32_t lp = pack_bf16(l0, l1);
        int mf = r >> 4, g8 = r & 7, ah = (r >> 3) & 1;
        int ks = kp >> 3, tt = kp & 3, kh = (kp >> 2) & 1;
        int off = (((mf * 16 + ks) * 32) + (g8 * 4 + tt)) * 4 + (ah + kh * 2);
        sAhi[off] = hp;
        sAlo[off] = lp;
    }
    __syncthreads();

    // ---- mainloop: D = Ah*Bh + Ah*Bl + Al*Bh ----
    float c[4][4][4];
    #pragma unroll
    for (int mf = 0; mf < 4; mf++)
        #pragma unroll
        for (int nb = 0; nb < 4; nb++)
            #pragma unroll
            for (int r = 0; r < 4; r++) c[mf][nb][r] = 0.f;

    #pragma unroll 1
    for (int ks = 0; ks < 16; ks++) {
        uint4 ahv[4], alv[4];
        #pragma unroll
        for (int mf = 0; mf < 4; mf++) {
            int fo = ((mf * 16 + ks) * 32 + lane) * 4;
            ahv[mf] = *(const uint4*)(sAhi + fo);
            alv[mf] = *(const uint4*)(sAlo + fo);
        }
        #pragma unroll
        for (int nb = 0; nb < 4; nb++) {
            int fidx = ((nw * 4 + nb) * 16 + ks) * 32 + lane;
            uint2 bh = g_Bh[fidx];
            uint2 bl = g_Bl[fidx];
            // product-major order: 4 independent accumulator chains between
            // reuses of the same c[mf][nb]
            #pragma unroll
            for (int mf = 0; mf < 4; mf++)
                mma16816(c[mf][nb], (const uint32_t*)&ahv[mf], bh.x, bh.y);
            #pragma unroll
            for (int mf = 0; mf < 4; mf++)
                mma16816(c[mf][nb], (const uint32_t*)&ahv[mf], bl.x, bl.y);
            #pragma unroll
            for (int mf = 0; mf < 4; mf++)
                mma16816(c[mf][nb], (const uint32_t*)&alv[mf], bh.x, bh.y);
        }
    }

    // ---- epilogue 1: bias + relu + tanh + dot(we_k) ----
    float rs[4][2];
    #pragma unroll
    for (int mf = 0; mf < 4; mf++) { rs[mf][0] = 0.f; rs[mf][1] = 0.f; }

    #pragma unroll
    for (int nb = 0; nb < 4; nb++) {
        int j0 = nw * 32 + nb * 8 + t * 2;
        float b0 = sBk[j0], b1 = sBk[j0 + 1];
        float w0 = sWe[j0], w1 = sWe[j0 + 1];
        #pragma unroll
        for (int mf = 0; mf < 4; mf++) {
            rs[mf][0] += ftanh_nn(fmaxf(c[mf][nb][0] + b0, 0.f)) * w0
                       + ftanh_nn(fmaxf(c[mf][nb][1] + b1, 0.f)) * w1;
            rs[mf][1] += ftanh_nn(fmaxf(c[mf][nb][2] + b0, 0.f)) * w0
                       + ftanh_nn(fmaxf(c[mf][nb][3] + b1, 0.f)) * w1;
        }
    }

    #pragma unroll
    for (int mf = 0; mf < 4; mf++) {
        #pragma unroll
        for (int h = 0; h < 2; h++) {
            float v = rs[mf][h];
            v += __shfl_xor_sync(0xffffffffu, v, 1);
            v += __shfl_xor_sync(0xffffffffu, v, 2);
            if (t == 0) sE[(mf * 16 + h * 8 + g) * 8 + nw] = v;
        }
    }
    __syncthreads();

    // ---- epilogue 2: exp (no max subtraction; energies bounded) + denom ----
    const int b = blockIdx.x >> 6;      // 64 blocks per batch
    if (tid < 64) {
        float e = 0.f;
        #pragma unroll
        for (int q = 0; q < 8; q++) e += sE[tid * 8 + q];
        int token = tokBase + tid;
        bool mv = (mask[token] != 0);
        // masked: energy = 1e-45 -> exp = 1.0f (ratio-identical to reference)
        float w = mv ? __expf(g_eq + e) : 1.0f;
        sW[tid] = w;
        // per-warp reduce -> one atomicAdd per 32 tokens
        float s = w;
        #pragma unroll
        for (int off = 16; off > 0; off >>= 1)
            s += __shfl_xor_sync(0xffffffffu, s, off);
        if (lane == 0) atomicAdd(&g_d[b], s);
    }
    __syncthreads();   // sW visible; sE reads done (sP may overwrite)

    // ---- epilogue 3: weighted partial from smem fragments (hi+lo = fp32) ----
    {
        int p = tid & 127;              // emb pair: e = 2p, 2p+1
        int rh = tid >> 7;              // row half: rows rh*32 .. rh*32+31
        int ks = p >> 3, tt = p & 3, kh = (p >> 2) & 1;
        float a0 = 0.f, a1 = 0.f;
        #pragma unroll 4
        for (int rr = 0; rr < 32; rr++) {
            int r = rh * 32 + rr;
            float wgt = sW[r];
            int mf = r >> 4, g8 = r & 7, ah = (r >> 3) & 1;
            int off = (((mf * 16 + ks) * 32) + (g8 * 4 + tt)) * 4 + (ah + kh * 2);
            float2 fh = unpack_bf16x2(sAhi[off]);
            float2 fl = unpack_bf16x2(sAlo[off]);
            a0 += wgt * (fh.x + fl.x);
            a1 += wgt * (fh.y + fl.y);
        }
        if (rh == 1) { sP[p * 2] = a0; sP[p * 2 + 1] = a1; }
        __syncthreads();
        if (rh == 0) {
            float* dst = g_partial + (size_t)blockIdx.x * EMB;
            dst[p * 2]     = a0 + sP[p * 2];
            dst[p * 2 + 1] = a1 + sP[p * 2 + 1];
        }
    }
}

// ---------------- finalize: sum 64 chunks per batch, divide by denom ----------------
__global__ void finalize(float* __restrict__ out) {
    int b = blockIdx.x, e = threadIdx.x;
    float s = 0.f;
    #pragma unroll 8
    for (int c = 0; c < 64; c++)
        s += g_partial[(size_t)(b * 64 + c) * EMB + e];
    out[b * EMB + e] = s / g_d[b];
}

// ---------------- launch ----------------
extern "C" void kernel_launch(void* const* d_in, const int* in_sizes, int n_in,
                              void* d_out, int out_size) {
    const float* WE     = (const float*)d_in[0];
    const int*   mask   = (const int*)d_in[1];
    const float* wquery = (const float*)d_in[2];
    const float* wq     = (const float*)d_in[3];
    const float* bq     = (const float*)d_in[4];
    const float* wk     = (const float*)d_in[5];
    const float* bk     = (const float*)d_in[6];
    const float* we     = (const float*)d_in[7];
    const float* be     = (const float*)d_in[8];
    float* out          = (float*)d_out;

    prep_eq<<<1, 256>>>(wquery, wq, bq, we, be);
    prep_wkB<<<64, 256>>>(wk);

    cudaFuncSetAttribute(energy_kernel,
                         cudaFuncAttributeMaxDynamicSharedMemorySize, SMEM_TOTAL);
    energy_kernel<<<(BSZ * SLEN) / 64, 256, SMEM_TOTAL>>>(WE, mask, bk, we);

    finalize<<<BSZ, 256>>>(out);
}

// round 16
// speedup vs baseline: 3.9983x; 1.1597x over previous
#include <cuda_runtime.h>
#include <cuda_bf16.h>
#include <cuda_fp16.h>
#include <cstdint>
#include <cstddef>

#define BSZ 32
#define SLEN 4096
#define EMB 256

// ---------------- device scratch ----------------
// B fragments (fp16), fragment-ordered: [nblk(32)][kstep(16)][lane(32)] -> uint2
__device__ uint2 g_Bh[32 * 16 * 32];
__device__ uint2 g_Bl[32 * 16 * 32];
__device__ float g_eq;
__device__ float g_d[BSZ];              // softmax denominators (atomic)
__device__ float g_accum[BSZ * EMB];    // output accumulators (atomic)

// ---------------- helpers ----------------
__device__ __forceinline__ uint32_t pack_h2(float a, float b) {
    __half2 h = __floats2half2_rn(a, b);
    return *(uint32_t*)&h;
}
__device__ __forceinline__ float2 unpack_h2(uint32_t v) {
    __half2 h = *(__half2*)&v;
    return __half22float2(h);
}

__device__ __forceinline__ void mma16816(float c[4], const uint32_t* a,
                                         uint32_t b0, uint32_t b1) {
    asm volatile(
        "mma.sync.aligned.m16n8k16.row.col.f32.f16.f16.f32 "
        "{%0,%1,%2,%3}, {%4,%5,%6,%7}, {%8,%9}, {%0,%1,%2,%3};"
        : "+f"(c[0]), "+f"(c[1]), "+f"(c[2]), "+f"(c[3])
        : "r"(a[0]), "r"(a[1]), "r"(a[2]), "r"(a[3]), "r"(b0), "r"(b1));
}

// fast tanh for x >= 0 (post-relu): 1 - 2/(e^{2x}+1)
__device__ __forceinline__ float ftanh_nn(float x) {
    float e = __expf(2.0f * x);
    return 1.0f - __fdividef(2.0f, e + 1.0f);
}

// ---------------- prep: e_q scalar + zero accumulators ----------------
__global__ void prep_eq(const float* __restrict__ wquery, const float* __restrict__ wq,
                        const float* __restrict__ bq, const float* __restrict__ we,
                        const float* __restrict__ be) {
    int tid = threadIdx.x;
    int w = tid >> 5, lane = tid & 31;

    if (tid < BSZ) g_d[tid] = 0.f;
    #pragma unroll
    for (int i = 0; i < BSZ; i++) g_accum[i * EMB + tid] = 0.f;

    float4 q0 = ((const float4*)wquery)[lane * 2];
    float4 q1 = ((const float4*)wquery)[lane * 2 + 1];

    float acc = 0.f;
    for (int r = w; r < EMB; r += 8) {
        const float4* row = (const float4*)(wq + (size_t)r * EMB);
        float4 a0 = row[lane * 2], a1 = row[lane * 2 + 1];
        float d = a0.x * q0.x + a0.y * q0.y + a0.z * q0.z + a0.w * q0.w
                + a1.x * q1.x + a1.y * q1.y + a1.z * q1.z + a1.w * q1.w;
        #pragma unroll
        for (int off = 16; off > 0; off >>= 1) d += __shfl_xor_sync(0xffffffffu, d, off);
        if (lane == 0) acc += tanhf(fmaxf(d + bq[r], 0.f)) * we[r];
    }
    __shared__ float red[8];
    if (lane == 0) red[w] = acc;
    __syncthreads();
    if (tid == 0) {
        float s = 0.f;
        #pragma unroll
        for (int q = 0; q < 8; q++) s += red[q];
        g_eq = s + be[0];
    }
}

// ---------------- prep: wk -> fp16 hi/lo B fragments ----------------
// B operand (col) for m16n8k16: lane(g,t) holds b0={B[t*2][g],B[t*2+1][g]},
// b1={B[t*2+8][g],B[t*2+9][g]}, with B[k][n] = wk[n][k].
__global__ void prep_wkB(const float* __restrict__ wk) {
    int idx = blockIdx.x * 256 + threadIdx.x;   // 0..16383
    int lane = idx & 31;
    int ks = (idx >> 5) & 15;
    int nblk = idx >> 9;
    int g = lane >> 2, t = lane & 3;
    int n = nblk * 8 + g;
    int k = ks * 16 + t * 2;
    const float* row = wk + n * EMB;
    float x0 = row[k], x1 = row[k + 1], x2 = row[k + 8], x3 = row[k + 9];

    __half h0 = __float2half_rn(x0), h1 = __float2half_rn(x1);
    __half h2 = __float2half_rn(x2), h3 = __float2half_rn(x3);
    float l0 = x0 - __half2float(h0), l1 = x1 - __half2float(h1);
    float l2 = x2 - __half2float(h2), l3 = x3 - __half2float(h3);

    uint2 bh, bl;
    bh.x = (uint32_t)__half_as_ushort(h0) | ((uint32_t)__half_as_ushort(h1) << 16);
    bh.y = (uint32_t)__half_as_ushort(h2) | ((uint32_t)__half_as_ushort(h3) << 16);
    bl.x = pack_h2(l0, l1);
    bl.y = pack_h2(l2, l3);
    g_Bh[idx] = bh;
    g_Bl[idx] = bl;
}

// ---------------- main: fused energy + exp + denom + weighted accumulate ----------------
// Block: 256 thr (8 warps), M=64 tokens, N=256 (warp nw owns a 32-col slice).
// A tile stored as fp16 hi plane (used by MMA) + fp16 lo plane (reconstruction only).
// GEMM: D = Ah*Bh + Ah*Bl  (error = A fp16 quantization ~2^-12)
#define SM_AH 0
#define SM_AL 32768
#define SM_BK 65536
#define SM_WE 66560
#define SM_SE 67584                      // [64][8] energy partials
#define SM_W  69632                      // [64] exp weights
#define SMEM_TOTAL (69632 + 256)

__global__ __launch_bounds__(256, 2)
void energy_kernel(const float* __restrict__ WE,
                   const int* __restrict__ mask,
                   const float* __restrict__ bk,
                   const float* __restrict__ we) {
    extern __shared__ unsigned char sm[];
    uint32_t* sAhi = (uint32_t*)(sm + SM_AH);
    uint32_t* sAlo = (uint32_t*)(sm + SM_AL);
    float* sBk = (float*)(sm + SM_BK);
    float* sWe = (float*)(sm + SM_WE);
    float* sE  = (float*)(sm + SM_SE);
    float* sW  = (float*)(sm + SM_W);

    const int tid = threadIdx.x;
    const int nw = tid >> 5;
    const int lane = tid & 31;
    const int g = lane >> 2, t = lane & 3;
    const int tokBase = blockIdx.x * 64;

    sBk[tid] = bk[tid];
    sWe[tid] = we[EMB + tid];

    // ---- convert A tile (64 x 256 fp32) -> fp16 hi/lo fragments in smem ----
    for (int idx = tid; idx < 8192; idx += 256) {
        int r = idx >> 7, kp = idx & 127;
        float2 f = *(const float2*)(WE + (size_t)(tokBase + r) * EMB + kp * 2);
        __half h0 = __float2half_rn(f.x);
        __half h1 = __float2half_rn(f.y);
        float l0 = f.x - __half2float(h0);
        float l1 = f.y - __half2float(h1);
        uint32_t hp = (uint32_t)__half_as_ushort(h0) |
                      ((uint32_t)__half_as_ushort(h1) << 16);
        uint32_t lp = pack_h2(l0, l1);
        int mf = r >> 4, g8 = r & 7, ah = (r >> 3) & 1;
        int ks = kp >> 3, tt = kp & 3, kh = (kp >> 2) & 1;
        int off = (((mf * 16 + ks) * 32) + (g8 * 4 + tt)) * 4 + (ah + kh * 2);
        sAhi[off] = hp;
        sAlo[off] = lp;
    }
    __syncthreads();

    // ---- mainloop: D = Ah*Bh + Ah*Bl ----
    float c[4][4][4];
    #pragma unroll
    for (int mf = 0; mf < 4; mf++)
        #pragma unroll
        for (int nb = 0; nb < 4; nb++)
            #pragma unroll
            for (int r = 0; r < 4; r++) c[mf][nb][r] = 0.f;

    #pragma unroll 1
    for (int ks = 0; ks < 16; ks++) {
        uint4 ahv[4];
        #pragma unroll
        for (int mf = 0; mf < 4; mf++) {
            int fo = ((mf * 16 + ks) * 32 + lane) * 4;
            ahv[mf] = *(const uint4*)(sAhi + fo);
        }
        #pragma unroll
        for (int nb = 0; nb < 4; nb++) {
            int fidx = ((nw * 4 + nb) * 16 + ks) * 32 + lane;
            uint2 bh = g_Bh[fidx];
            uint2 bl = g_Bl[fidx];
            #pragma unroll
            for (int mf = 0; mf < 4; mf++)
                mma16816(c[mf][nb], (const uint32_t*)&ahv[mf], bh.x, bh.y);
            #pragma unroll
            for (int mf = 0; mf < 4; mf++)
                mma16816(c[mf][nb], (const uint32_t*)&ahv[mf], bl.x, bl.y);
        }
    }

    // ---- epilogue 1: bias + relu + tanh + dot(we_k) ----
    float rs[4][2];
    #pragma unroll
    for (int mf = 0; mf < 4; mf++) { rs[mf][0] = 0.f; rs[mf][1] = 0.f; }

    #pragma unroll
    for (int nb = 0; nb < 4; nb++) {
        int j0 = nw * 32 + nb * 8 + t * 2;
        float b0 = sBk[j0], b1 = sBk[j0 + 1];
        float w0 = sWe[j0], w1 = sWe[j0 + 1];
        #pragma unroll
        for (int mf = 0; mf < 4; mf++) {
            rs[mf][0] += ftanh_nn(fmaxf(c[mf][nb][0] + b0, 0.f)) * w0
                       + ftanh_nn(fmaxf(c[mf][nb][1] + b1, 0.f)) * w1;
            rs[mf][1] += ftanh_nn(fmaxf(c[mf][nb][2] + b0, 0.f)) * w0
                       + ftanh_nn(fmaxf(c[mf][nb][3] + b1, 0.f)) * w1;
        }
    }

    #pragma unroll
    for (int mf = 0; mf < 4; mf++) {
        #pragma unroll
        for (int h = 0; h < 2; h++) {
            float v = rs[mf][h];
            v += __shfl_xor_sync(0xffffffffu, v, 1);
            v += __shfl_xor_sync(0xffffffffu, v, 2);
            if (t == 0) sE[(mf * 16 + h * 8 + g) * 8 + nw] = v;
        }
    }
    __syncthreads();

    // ---- epilogue 2: exp (no max; energies bounded) + denom ----
    const int b = blockIdx.x >> 6;      // 64 blocks per batch
    if (tid < 64) {
        float e = 0.f;
        #pragma unroll
        for (int q = 0; q < 8; q++) e += sE[tid * 8 + q];
        int token = tokBase + tid;
        bool mv = (mask[token] != 0);
        // masked: energy = 1e-45 -> exp = 1.0 (ratio-identical to reference)
        float w = mv ? __expf(g_eq + e) : 1.0f;
        sW[tid] = w;
        float s = w;
        #pragma unroll
        for (int off = 16; off > 0; off >>= 1)
            s += __shfl_xor_sync(0xffffffffu, s, off);
        if (lane == 0) atomicAdd(&g_d[b], s);
    }
    __syncthreads();

    // ---- epilogue 3: weighted accumulate from smem (hi+lo ~= fp32) ----
    {
        int p = tid & 127;              // emb pair: e = 2p, 2p+1
        int rh = tid >> 7;              // row half
        int ks = p >> 3, tt = p & 3, kh = (p >> 2) & 1;
        float a0 = 0.f, a1 = 0.f;
        #pragma unroll 4
        for (int rr = 0; rr < 32; rr++) {
            int r = rh * 32 + rr;
            float wgt = sW[r];
            int mf = r >> 4, g8 = r & 7, ah = (r >> 3) & 1;
            int off = (((mf * 16 + ks) * 32) + (g8 * 4 + tt)) * 4 + (ah + kh * 2);
            float2 fh = unpack_h2(sAhi[off]);
            float2 fl = unpack_h2(sAlo[off]);
            a0 += wgt * (fh.x + fl.x);
            a1 += wgt * (fh.y + fl.y);
        }
        atomicAdd(&g_accum[b * EMB + p * 2],     a0);
        atomicAdd(&g_accum[b * EMB + p * 2 + 1], a1);
    }
}

// ---------------- finalize: divide ----------------
__global__ void finalize(float* __restrict__ out) {
    int b = blockIdx.x, e = threadIdx.x;
    out[b * EMB + e] = g_accum[b * EMB + e] / g_d[b];
}

// ---------------- launch ----------------
extern "C" void kernel_launch(void* const* d_in, const int* in_sizes, int n_in,
                              void* d_out, int out_size) {
    const float* WE     = (const float*)d_in[0];
    const int*   mask   = (const int*)d_in[1];
    const float* wquery = (const float*)d_in[2];
    const float* wq     = (const float*)d_in[3];
    const float* bq     = (const float*)d_in[4];
    const float* wk     = (const float*)d_in[5];
    const float* bk     = (const float*)d_in[6];
    const float* we     = (const float*)d_in[7];
    const float* be     = (const float*)d_in[8];
    float* out          = (float*)d_out;

    prep_eq<<<1, 256>>>(wquery, wq, bq, we, be);
    prep_wkB<<<64, 256>>>(wk);

    cudaFuncSetAttribute(energy_kernel,
                         cudaFuncAttributeMaxDynamicSharedMemorySize, SMEM_TOTAL);
    energy_kernel<<<(BSZ * SLEN) / 64, 256, SMEM_TOTAL>>>(WE, mask, bk, we);

    finalize<<<BSZ, 256>>>(out);
}